// round 2
// baseline (speedup 1.0000x reference)
#include <cuda_runtime.h>
#include <cstdint>
#include <math.h>

// Problem constants
#define B_  4
#define S_  2048
#define H_  16
#define D_  64
#define F_  1024
#define M_  (B_*S_)   // 8192 rows

// ---------------------------------------------------------------------------
// Scratch (static device globals -- no allocation allowed)
// ---------------------------------------------------------------------------
__device__ float g_Q[B_*H_*S_*D_];   // [bh][s][d], Q pre-scaled by 1/sqrt(64)
__device__ float g_K[B_*H_*S_*D_];
__device__ float g_V[B_*H_*S_*D_];
__device__ float g_O[M_*F_];         // [b*S+s][h*64+d]

// ---------------------------------------------------------------------------
// TF32 helpers
// ---------------------------------------------------------------------------
__device__ __forceinline__ uint32_t f2tf32(float x) {
    uint32_t y;
    asm("cvt.rna.tf32.f32 %0, %1;" : "=r"(y) : "f"(x));
    return y;
}

__device__ __forceinline__ void mma_tf32(float c[4],
                                         uint32_t a0, uint32_t a1, uint32_t a2, uint32_t a3,
                                         uint32_t b0, uint32_t b1) {
    asm volatile(
        "mma.sync.aligned.m16n8k8.row.col.f32.tf32.tf32.f32 "
        "{%0,%1,%2,%3},{%4,%5,%6,%7},{%8,%9},{%0,%1,%2,%3};"
        : "+f"(c[0]), "+f"(c[1]), "+f"(c[2]), "+f"(c[3])
        : "r"(a0), "r"(a1), "r"(a2), "r"(a3), "r"(b0), "r"(b1));
}

// ---------------------------------------------------------------------------
// GEMM: C[128x128 tile] = A[M x 1024] * B[1024 x 1024]   (TF32 mma)
// 256 threads, warps in 2x4 grid, each warp 64x32 (4 mtiles x 4 ntiles).
// Shared by QKV projection and output projection kernels.
// ---------------------------------------------------------------------------
#define SA_STRIDE 36    // 36 % 32 == 4 -> conflict-free A-fragment LDS
#define SB_STRIDE 136   // 136 % 32 == 8 -> conflict-free B-fragment LDS

struct GemmSmem {
    uint32_t sA[128 * SA_STRIDE];
    uint32_t sB[32 * SB_STRIDE];
};

__device__ __forceinline__ void gemm_mainloop(const float* __restrict__ A,
                                              const float* __restrict__ Bm,
                                              int m0, int n0,
                                              GemmSmem& sm,
                                              float acc[4][4][4]) {
    const int tid  = threadIdx.x;
    const int warp = tid >> 5, lane = tid & 31;
    const int wm = (warp >> 2) * 64, wn = (warp & 3) * 32;
    const int g = lane >> 2, t = lane & 3;

    #pragma unroll
    for (int mt = 0; mt < 4; mt++)
        #pragma unroll
        for (int nt = 0; nt < 4; nt++)
            #pragma unroll
            for (int c = 0; c < 4; c++)
                acc[mt][nt][c] = 0.0f;

    for (int k0 = 0; k0 < 1024; k0 += 32) {
        // --- A tile: rows m0..m0+127, cols k0..k0+31 ---
        {
            int r  = tid >> 3;          // 0..31
            int c4 = (tid & 7) * 4;     // 0..28
            #pragma unroll
            for (int p = 0; p < 4; p++) {
                const float4 v = *(const float4*)(A + (size_t)(m0 + r + p * 32) * 1024 + k0 + c4);
                uint32_t* d = &sm.sA[(r + p * 32) * SA_STRIDE + c4];
                d[0] = f2tf32(v.x); d[1] = f2tf32(v.y);
                d[2] = f2tf32(v.z); d[3] = f2tf32(v.w);
            }
        }
        // --- B tile: rows k0..k0+31, cols n0..n0+127 ---
        {
            int r  = tid >> 5;          // 0..7
            int c4 = (tid & 31) * 4;    // 0..124
            #pragma unroll
            for (int p = 0; p < 4; p++) {
                const float4 v = *(const float4*)(Bm + (size_t)(k0 + r + p * 8) * 1024 + n0 + c4);
                uint32_t* d = &sm.sB[(r + p * 8) * SB_STRIDE + c4];
                d[0] = f2tf32(v.x); d[1] = f2tf32(v.y);
                d[2] = f2tf32(v.z); d[3] = f2tf32(v.w);
            }
        }
        __syncthreads();

        #pragma unroll
        for (int ks = 0; ks < 4; ks++) {
            uint32_t af[4][4];
            uint32_t bf[4][2];
            #pragma unroll
            for (int mt = 0; mt < 4; mt++) {
                const uint32_t* b0p = &sm.sA[(wm + mt * 16 + g) * SA_STRIDE + ks * 8 + t];
                const uint32_t* b1p = b0p + 8 * SA_STRIDE;
                af[mt][0] = b0p[0];
                af[mt][1] = b1p[0];
                af[mt][2] = b0p[4];
                af[mt][3] = b1p[4];
            }
            #pragma unroll
            for (int nt = 0; nt < 4; nt++) {
                const uint32_t* bp = &sm.sB[(ks * 8 + t) * SB_STRIDE + wn + nt * 8 + g];
                bf[nt][0] = bp[0];
                bf[nt][1] = bp[4 * SB_STRIDE];
            }
            #pragma unroll
            for (int mt = 0; mt < 4; mt++)
                #pragma unroll
                for (int nt = 0; nt < 4; nt++)
                    mma_tf32(acc[mt][nt], af[mt][0], af[mt][1], af[mt][2], af[mt][3],
                             bf[nt][0], bf[nt][1]);
        }
        __syncthreads();
    }
}

// ---------------------------------------------------------------------------
// Kernel 1: QKV projection.  blockIdx.z selects {Q,K,V}.
// Epilogue writes [bh][s][d] layout; Q gets (acc+bias)*0.125.
// ---------------------------------------------------------------------------
__global__ void __launch_bounds__(256, 1)
qkv_gemm_kernel(const float* __restrict__ X,
                const float* __restrict__ Wq, const float* __restrict__ bq,
                const float* __restrict__ Wk, const float* __restrict__ bk,
                const float* __restrict__ Wv, const float* __restrict__ bv) {
    __shared__ GemmSmem sm;
    const int z = blockIdx.z;
    const float* W    = (z == 0) ? Wq : ((z == 1) ? Wk : Wv);
    const float* bias = (z == 0) ? bq : ((z == 1) ? bk : bv);
    float* Out        = (z == 0) ? g_Q : ((z == 1) ? g_K : g_V);
    const float scale = (z == 0) ? 0.125f : 1.0f;

    const int m0 = blockIdx.y * 128;
    const int n0 = blockIdx.x * 128;

    float acc[4][4][4];
    gemm_mainloop(X, W, m0, n0, sm, acc);

    const int lane = threadIdx.x & 31, warp = threadIdx.x >> 5;
    const int wm = (warp >> 2) * 64, wn = (warp & 3) * 32;
    const int g = lane >> 2, t = lane & 3;

    #pragma unroll
    for (int mt = 0; mt < 4; mt++) {
        #pragma unroll
        for (int nt = 0; nt < 4; nt++) {
            const int nbase = n0 + wn + nt * 8 + 2 * t;
            #pragma unroll
            for (int c = 0; c < 4; c++) {
                const int m  = m0 + wm + mt * 16 + g + ((c >= 2) ? 8 : 0);
                const int nn = nbase + (c & 1);
                const int b  = m >> 11, s = m & 2047;
                const int h  = nn >> 6, d = nn & 63;
                const float val = (acc[mt][nt][c] + bias[nn]) * scale;
                Out[(((b * H_ + h) * S_) + s) * D_ + d] = val;
            }
        }
    }
}

// ---------------------------------------------------------------------------
// Kernel 3: output projection.  out[m][n] = g_O[m][:] . Wo[:][n] + bo[n]
// ---------------------------------------------------------------------------
__global__ void __launch_bounds__(256, 1)
out_gemm_kernel(const float* __restrict__ Wo, const float* __restrict__ bo,
                float* __restrict__ out) {
    __shared__ GemmSmem sm;
    const int m0 = blockIdx.y * 128;
    const int n0 = blockIdx.x * 128;

    float acc[4][4][4];
    gemm_mainloop(g_O, Wo, m0, n0, sm, acc);

    const int lane = threadIdx.x & 31, warp = threadIdx.x >> 5;
    const int wm = (warp >> 2) * 64, wn = (warp & 3) * 32;
    const int g = lane >> 2, t = lane & 3;

    #pragma unroll
    for (int mt = 0; mt < 4; mt++) {
        #pragma unroll
        for (int nt = 0; nt < 4; nt++) {
            const int nbase = n0 + wn + nt * 8 + 2 * t;
            #pragma unroll
            for (int c = 0; c < 4; c++) {
                const int m  = m0 + wm + mt * 16 + g + ((c >= 2) ? 8 : 0);
                const int nn = nbase + (c & 1);
                out[(size_t)m * 1024 + nn] = acc[mt][nt][c] + bo[nn];
            }
        }
    }
}

// ---------------------------------------------------------------------------
// Kernel 2: flash attention.  grid = (16 q-tiles, 64 bh).  256 threads.
// Each warp owns 16 Q rows; CTA covers 128 Q rows x full K sweep (16x128).
// ---------------------------------------------------------------------------
#define QSTR 68    // 68 % 32 == 4
#define KSTR 68
#define VSTR 72    // 72 % 32 == 8
#define PSTR 132   // 132 % 32 == 4
#define ATTN_SMEM_BYTES ((128*QSTR + 128*KSTR + 128*VSTR + 128*PSTR) * 4)  // 174080

__device__ __forceinline__ void load_tile64(uint32_t* dst, const float* __restrict__ src,
                                            int stride, int tid) {
    #pragma unroll
    for (int p = 0; p < 8; p++) {
        const int i  = tid + p * 256;   // 0..2047 float4s
        const int r  = i >> 4;
        const int c4 = (i & 15) * 4;
        const float4 v = *(const float4*)(src + r * 64 + c4);
        uint32_t* d = dst + r * stride + c4;
        d[0] = f2tf32(v.x); d[1] = f2tf32(v.y);
        d[2] = f2tf32(v.z); d[3] = f2tf32(v.w);
    }
}

__global__ void __launch_bounds__(256, 1)
attn_kernel() {
    extern __shared__ uint32_t smem[];
    uint32_t* sQ = smem;
    uint32_t* sK = sQ + 128 * QSTR;
    uint32_t* sV = sK + 128 * KSTR;
    uint32_t* sP = sV + 128 * VSTR;

    const int bh = blockIdx.y;          // 0..63
    const int q0 = blockIdx.x * 128;
    const float* Qg = g_Q + (size_t)bh * S_ * D_ + (size_t)q0 * D_;
    const float* Kg = g_K + (size_t)bh * S_ * D_;
    const float* Vg = g_V + (size_t)bh * S_ * D_;

    const int tid = threadIdx.x;
    const int warp = tid >> 5, lane = tid & 31;
    const int g = lane >> 2, t = lane & 3;
    const int wr = warp * 16;           // this warp's row base in the 128-row tile

    load_tile64(sQ, Qg, QSTR, tid);

    float m_i[2] = { -INFINITY, -INFINITY };
    float l_i[2] = { 0.0f, 0.0f };
    float o[8][4];
    #pragma unroll
    for (int nt = 0; nt < 8; nt++)
        #pragma unroll
        for (int c = 0; c < 4; c++) o[nt][c] = 0.0f;

    for (int kt = 0; kt < 16; kt++) {
        __syncthreads();   // previous iteration's sK/sV reads complete
        load_tile64(sK, Kg + (size_t)kt * 128 * 64, KSTR, tid);
        load_tile64(sV, Vg + (size_t)kt * 128 * 64, VSTR, tid);
        __syncthreads();   // sQ (first iter) + sK/sV visible

        // ---- S = Q * K^T : warp computes 16 x 128 scores ----
        float s[16][4];
        #pragma unroll
        for (int nt = 0; nt < 16; nt++)
            #pragma unroll
            for (int c = 0; c < 4; c++) s[nt][c] = 0.0f;

        #pragma unroll
        for (int ks = 0; ks < 8; ks++) {
            const uint32_t* a0p = &sQ[(wr + g) * QSTR + ks * 8 + t];
            const uint32_t* a1p = a0p + 8 * QSTR;
            const uint32_t a0 = a0p[0], a1 = a1p[0], a2 = a0p[4], a3 = a1p[4];
            #pragma unroll
            for (int nt = 0; nt < 16; nt++) {
                const uint32_t* bp = &sK[(nt * 8 + g) * KSTR + ks * 8 + t];
                mma_tf32(s[nt], a0, a1, a2, a3, bp[0], bp[4]);
            }
        }

        // ---- online softmax ----
        float mx0 = -INFINITY, mx1 = -INFINITY;
        #pragma unroll
        for (int nt = 0; nt < 16; nt++) {
            mx0 = fmaxf(mx0, fmaxf(s[nt][0], s[nt][1]));
            mx1 = fmaxf(mx1, fmaxf(s[nt][2], s[nt][3]));
        }
        mx0 = fmaxf(mx0, __shfl_xor_sync(0xffffffffu, mx0, 1));
        mx0 = fmaxf(mx0, __shfl_xor_sync(0xffffffffu, mx0, 2));
        mx1 = fmaxf(mx1, __shfl_xor_sync(0xffffffffu, mx1, 1));
        mx1 = fmaxf(mx1, __shfl_xor_sync(0xffffffffu, mx1, 2));

        const float mnew0 = fmaxf(m_i[0], mx0);
        const float mnew1 = fmaxf(m_i[1], mx1);
        const float sc0 = __expf(m_i[0] - mnew0);
        const float sc1 = __expf(m_i[1] - mnew1);

        float sum0 = 0.0f, sum1 = 0.0f;
        uint32_t* pr0 = &sP[(wr + g) * PSTR + 2 * t];
        uint32_t* pr1 = pr0 + 8 * PSTR;
        #pragma unroll
        for (int nt = 0; nt < 16; nt++) {
            const float p0 = __expf(s[nt][0] - mnew0);
            const float p1 = __expf(s[nt][1] - mnew0);
            const float p2 = __expf(s[nt][2] - mnew1);
            const float p3 = __expf(s[nt][3] - mnew1);
            sum0 += p0 + p1;
            sum1 += p2 + p3;
            pr0[nt * 8 + 0] = f2tf32(p0);
            pr0[nt * 8 + 1] = f2tf32(p1);
            pr1[nt * 8 + 0] = f2tf32(p2);
            pr1[nt * 8 + 1] = f2tf32(p3);
        }
        sum0 += __shfl_xor_sync(0xffffffffu, sum0, 1);
        sum0 += __shfl_xor_sync(0xffffffffu, sum0, 2);
        sum1 += __shfl_xor_sync(0xffffffffu, sum1, 1);
        sum1 += __shfl_xor_sync(0xffffffffu, sum1, 2);

        l_i[0] = l_i[0] * sc0 + sum0;
        l_i[1] = l_i[1] * sc1 + sum1;
        m_i[0] = mnew0;
        m_i[1] = mnew1;

        #pragma unroll
        for (int nt = 0; nt < 8; nt++) {
            o[nt][0] *= sc0; o[nt][1] *= sc0;
            o[nt][2] *= sc1; o[nt][3] *= sc1;
        }
        __syncwarp();      // sP writes (own rows) visible to own warp

        // ---- O += P * V : warp's 16 rows x 64 cols, K = 128 ----
        #pragma unroll
        for (int ks = 0; ks < 16; ks++) {
            const uint32_t* a0p = &sP[(wr + g) * PSTR + ks * 8 + t];
            const uint32_t* a1p = a0p + 8 * PSTR;
            const uint32_t a0 = a0p[0], a1 = a1p[0], a2 = a0p[4], a3 = a1p[4];
            #pragma unroll
            for (int nt = 0; nt < 8; nt++) {
                const uint32_t* bp = &sV[(ks * 8 + t) * VSTR + nt * 8 + g];
                mma_tf32(o[nt], a0, a1, a2, a3, bp[0], bp[4 * VSTR]);
            }
        }
    }

    // ---- epilogue: O / l -> g_O [b*S+s][h*64+d] ----
    const float inv0 = 1.0f / l_i[0];
    const float inv1 = 1.0f / l_i[1];
    const int b = bh >> 4, h = bh & 15;
    const int row0 = b * S_ + q0 + wr + g;
    const int row1 = row0 + 8;
    #pragma unroll
    for (int nt = 0; nt < 8; nt++) {
        const int n = h * 64 + nt * 8 + 2 * t;
        g_O[(size_t)row0 * 1024 + n]     = o[nt][0] * inv0;
        g_O[(size_t)row0 * 1024 + n + 1] = o[nt][1] * inv0;
        g_O[(size_t)row1 * 1024 + n]     = o[nt][2] * inv1;
        g_O[(size_t)row1 * 1024 + n + 1] = o[nt][3] * inv1;
    }
}

// ---------------------------------------------------------------------------
// kernel_launch
// ---------------------------------------------------------------------------
extern "C" void kernel_launch(void* const* d_in, const int* in_sizes, int n_in,
                              void* d_out, int out_size) {
    const float* X  = (const float*)d_in[0];
    const float* Wq = (const float*)d_in[1];
    const float* bq = (const float*)d_in[2];
    const float* Wk = (const float*)d_in[3];
    const float* bk = (const float*)d_in[4];
    const float* Wv = (const float*)d_in[5];
    const float* bv = (const float*)d_in[6];
    const float* Wo = (const float*)d_in[7];
    const float* bo = (const float*)d_in[8];
    float* out = (float*)d_out;

    cudaFuncSetAttribute(attn_kernel, cudaFuncAttributeMaxDynamicSharedMemorySize,
                         ATTN_SMEM_BYTES);

    qkv_gemm_kernel<<<dim3(8, 64, 3), 256>>>(X, Wq, bq, Wk, bk, Wv, bv);
    attn_kernel<<<dim3(16, 64), 256, ATTN_SMEM_BYTES>>>();
    out_gemm_kernel<<<dim3(8, 64), 256>>>(Wo, bo, out);
}

// round 5
// speedup vs baseline: 1.0047x; 1.0047x over previous
#include <cuda_runtime.h>
#include <cstdint>
#include <math.h>

// Problem constants
#define B_  4
#define S_  2048
#define H_  16
#define D_  64
#define F_  1024
#define M_  (B_*S_)   // 8192 rows

// ---------------------------------------------------------------------------
// Scratch (static device globals -- no allocation allowed)
// ---------------------------------------------------------------------------
__device__ float g_Q[B_*H_*S_*D_];   // [bh][s][d], Q pre-scaled by 1/sqrt(64)
__device__ float g_K[B_*H_*S_*D_];
__device__ float g_V[B_*H_*S_*D_];
__device__ float g_O[M_*F_];         // [b*S+s][h*64+d]

// ---------------------------------------------------------------------------
// TF32 helpers
// ---------------------------------------------------------------------------
__device__ __forceinline__ uint32_t f2tf32(float x) {
    uint32_t y;
    asm("cvt.rna.tf32.f32 %0, %1;" : "=r"(y) : "f"(x));
    return y;
}

__device__ __forceinline__ void mma_tf32(float c[4],
                                         uint32_t a0, uint32_t a1, uint32_t a2, uint32_t a3,
                                         uint32_t b0, uint32_t b1) {
    asm volatile(
        "mma.sync.aligned.m16n8k8.row.col.f32.tf32.tf32.f32 "
        "{%0,%1,%2,%3},{%4,%5,%6,%7},{%8,%9},{%0,%1,%2,%3};"
        : "+f"(c[0]), "+f"(c[1]), "+f"(c[2]), "+f"(c[3])
        : "r"(a0), "r"(a1), "r"(a2), "r"(a3), "r"(b0), "r"(b1));
}

// ---------------------------------------------------------------------------
// GEMM: C[128x128 tile] = A[M x 1024] * B[1024 x 1024]   (TF32 mma)
// 256 threads, warps in 2x4 grid, each warp 64x32 (4 mtiles x 4 ntiles).
// Shared by QKV projection and output projection kernels.
// ---------------------------------------------------------------------------
#define SA_STRIDE 36    // 36 % 32 == 4 -> conflict-free A-fragment LDS
#define SB_STRIDE 136   // 136 % 32 == 8 -> conflict-free B-fragment LDS

struct GemmSmem {
    uint32_t sA[128 * SA_STRIDE];
    uint32_t sB[32 * SB_STRIDE];
};

__device__ __forceinline__ void gemm_mainloop(const float* __restrict__ A,
                                              const float* __restrict__ Bm,
                                              int m0, int n0,
                                              GemmSmem& sm,
                                              float acc[4][4][4]) {
    const int tid  = threadIdx.x;
    const int warp = tid >> 5, lane = tid & 31;
    const int wm = (warp >> 2) * 64, wn = (warp & 3) * 32;
    const int g = lane >> 2, t = lane & 3;

    #pragma unroll
    for (int mt = 0; mt < 4; mt++)
        #pragma unroll
        for (int nt = 0; nt < 4; nt++)
            #pragma unroll
            for (int c = 0; c < 4; c++)
                acc[mt][nt][c] = 0.0f;

    for (int k0 = 0; k0 < 1024; k0 += 32) {
        // --- A tile: rows m0..m0+127, cols k0..k0+31 ---
        {
            int r  = tid >> 3;          // 0..31
            int c4 = (tid & 7) * 4;     // 0..28
            #pragma unroll
            for (int p = 0; p < 4; p++) {
                const float4 v = *(const float4*)(A + (size_t)(m0 + r + p * 32) * 1024 + k0 + c4);
                uint32_t* d = &sm.sA[(r + p * 32) * SA_STRIDE + c4];
                d[0] = f2tf32(v.x); d[1] = f2tf32(v.y);
                d[2] = f2tf32(v.z); d[3] = f2tf32(v.w);
            }
        }
        // --- B tile: rows k0..k0+31, cols n0..n0+127 ---
        {
            int r  = tid >> 5;          // 0..7
            int c4 = (tid & 31) * 4;    // 0..124
            #pragma unroll
            for (int p = 0; p < 4; p++) {
                const float4 v = *(const float4*)(Bm + (size_t)(k0 + r + p * 8) * 1024 + n0 + c4);
                uint32_t* d = &sm.sB[(r + p * 8) * SB_STRIDE + c4];
                d[0] = f2tf32(v.x); d[1] = f2tf32(v.y);
                d[2] = f2tf32(v.z); d[3] = f2tf32(v.w);
            }
        }
        __syncthreads();

        #pragma unroll
        for (int ks = 0; ks < 4; ks++) {
            uint32_t af[4][4];
            uint32_t bf[4][2];
            #pragma unroll
            for (int mt = 0; mt < 4; mt++) {
                const uint32_t* b0p = &sm.sA[(wm + mt * 16 + g) * SA_STRIDE + ks * 8 + t];
                const uint32_t* b1p = b0p + 8 * SA_STRIDE;
                af[mt][0] = b0p[0];
                af[mt][1] = b1p[0];
                af[mt][2] = b0p[4];
                af[mt][3] = b1p[4];
            }
            #pragma unroll
            for (int nt = 0; nt < 4; nt++) {
                const uint32_t* bp = &sm.sB[(ks * 8 + t) * SB_STRIDE + wn + nt * 8 + g];
                bf[nt][0] = bp[0];
                bf[nt][1] = bp[4 * SB_STRIDE];
            }
            #pragma unroll
            for (int mt = 0; mt < 4; mt++)
                #pragma unroll
                for (int nt = 0; nt < 4; nt++)
                    mma_tf32(acc[mt][nt], af[mt][0], af[mt][1], af[mt][2], af[mt][3],
                             bf[nt][0], bf[nt][1]);
        }
        __syncthreads();
    }
}

// ---------------------------------------------------------------------------
// Kernel 1: QKV projection.  blockIdx.z selects {Q,K,V}.
// Epilogue writes [bh][s][d] layout; Q gets (acc+bias)*0.125.
// ---------------------------------------------------------------------------
__global__ void __launch_bounds__(256, 1)
qkv_gemm_kernel(const float* __restrict__ X,
                const float* __restrict__ Wq, const float* __restrict__ bq,
                const float* __restrict__ Wk, const float* __restrict__ bk,
                const float* __restrict__ Wv, const float* __restrict__ bv) {
    __shared__ GemmSmem sm;
    const int z = blockIdx.z;
    const float* W    = (z == 0) ? Wq : ((z == 1) ? Wk : Wv);
    const float* bias = (z == 0) ? bq : ((z == 1) ? bk : bv);
    float* Out        = (z == 0) ? g_Q : ((z == 1) ? g_K : g_V);
    const float scale = (z == 0) ? 0.125f : 1.0f;

    const int m0 = blockIdx.y * 128;
    const int n0 = blockIdx.x * 128;

    float acc[4][4][4];
    gemm_mainloop(X, W, m0, n0, sm, acc);

    const int lane = threadIdx.x & 31, warp = threadIdx.x >> 5;
    const int wm = (warp >> 2) * 64, wn = (warp & 3) * 32;
    const int g = lane >> 2, t = lane & 3;

    #pragma unroll
    for (int mt = 0; mt < 4; mt++) {
        #pragma unroll
        for (int nt = 0; nt < 4; nt++) {
            const int nbase = n0 + wn + nt * 8 + 2 * t;
            #pragma unroll
            for (int c = 0; c < 4; c++) {
                const int m  = m0 + wm + mt * 16 + g + ((c >= 2) ? 8 : 0);
                const int nn = nbase + (c & 1);
                const int b  = m >> 11, s = m & 2047;
                const int h  = nn >> 6, d = nn & 63;
                const float val = (acc[mt][nt][c] + bias[nn]) * scale;
                Out[(((b * H_ + h) * S_) + s) * D_ + d] = val;
            }
        }
    }
}

// ---------------------------------------------------------------------------
// Kernel 3: output projection.  out[m][n] = g_O[m][:] . Wo[:][n] + bo[n]
// ---------------------------------------------------------------------------
__global__ void __launch_bounds__(256, 1)
out_gemm_kernel(const float* __restrict__ Wo, const float* __restrict__ bo,
                float* __restrict__ out) {
    __shared__ GemmSmem sm;
    const int m0 = blockIdx.y * 128;
    const int n0 = blockIdx.x * 128;

    float acc[4][4][4];
    gemm_mainloop(g_O, Wo, m0, n0, sm, acc);

    const int lane = threadIdx.x & 31, warp = threadIdx.x >> 5;
    const int wm = (warp >> 2) * 64, wn = (warp & 3) * 32;
    const int g = lane >> 2, t = lane & 3;

    #pragma unroll
    for (int mt = 0; mt < 4; mt++) {
        #pragma unroll
        for (int nt = 0; nt < 4; nt++) {
            const int nbase = n0 + wn + nt * 8 + 2 * t;
            #pragma unroll
            for (int c = 0; c < 4; c++) {
                const int m  = m0 + wm + mt * 16 + g + ((c >= 2) ? 8 : 0);
                const int nn = nbase + (c & 1);
                out[(size_t)m * 1024 + nn] = acc[mt][nt][c] + bo[nn];
            }
        }
    }
}

// ---------------------------------------------------------------------------
// Kernel 2: flash attention.  grid = (16 q-tiles, 64 bh).  256 threads.
// Each warp owns 16 Q rows; CTA covers 128 Q rows x full K sweep (16x128).
// ---------------------------------------------------------------------------
#define QSTR 68    // 68 % 32 == 4
#define KSTR 68
#define VSTR 72    // 72 % 32 == 8
#define PSTR 132   // 132 % 32 == 4
#define ATTN_SMEM_BYTES ((128*QSTR + 128*KSTR + 128*VSTR + 128*PSTR) * 4)  // 174080

__device__ __forceinline__ void load_tile64(uint32_t* dst, const float* __restrict__ src,
                                            int stride, int tid) {
    #pragma unroll
    for (int p = 0; p < 8; p++) {
        const int i  = tid + p * 256;   // 0..2047 float4s
        const int r  = i >> 4;
        const int c4 = (i & 15) * 4;
        const float4 v = *(const float4*)(src + r * 64 + c4);
        uint32_t* d = dst + r * stride + c4;
        d[0] = f2tf32(v.x); d[1] = f2tf32(v.y);
        d[2] = f2tf32(v.z); d[3] = f2tf32(v.w);
    }
}

__global__ void __launch_bounds__(256, 1)
attn_kernel() {
    extern __shared__ uint32_t smem[];
    uint32_t* sQ = smem;
    uint32_t* sK = sQ + 128 * QSTR;
    uint32_t* sV = sK + 128 * KSTR;
    uint32_t* sP = sV + 128 * VSTR;

    const int bh = blockIdx.y;          // 0..63
    const int q0 = blockIdx.x * 128;
    const float* Qg = g_Q + (size_t)bh * S_ * D_ + (size_t)q0 * D_;
    const float* Kg = g_K + (size_t)bh * S_ * D_;
    const float* Vg = g_V + (size_t)bh * S_ * D_;

    const int tid = threadIdx.x;
    const int warp = tid >> 5, lane = tid & 31;
    const int g = lane >> 2, t = lane & 3;
    const int wr = warp * 16;           // this warp's row base in the 128-row tile

    load_tile64(sQ, Qg, QSTR, tid);

    float m_i[2] = { -INFINITY, -INFINITY };
    float l_i[2] = { 0.0f, 0.0f };
    float o[8][4];
    #pragma unroll
    for (int nt = 0; nt < 8; nt++)
        #pragma unroll
        for (int c = 0; c < 4; c++) o[nt][c] = 0.0f;

    for (int kt = 0; kt < 16; kt++) {
        __syncthreads();   // previous iteration's sK/sV reads complete
        load_tile64(sK, Kg + (size_t)kt * 128 * 64, KSTR, tid);
        load_tile64(sV, Vg + (size_t)kt * 128 * 64, VSTR, tid);
        __syncthreads();   // sQ (first iter) + sK/sV visible

        // ---- S = Q * K^T : warp computes 16 x 128 scores ----
        float s[16][4];
        #pragma unroll
        for (int nt = 0; nt < 16; nt++)
            #pragma unroll
            for (int c = 0; c < 4; c++) s[nt][c] = 0.0f;

        #pragma unroll
        for (int ks = 0; ks < 8; ks++) {
            const uint32_t* a0p = &sQ[(wr + g) * QSTR + ks * 8 + t];
            const uint32_t* a1p = a0p + 8 * QSTR;
            const uint32_t a0 = a0p[0], a1 = a1p[0], a2 = a0p[4], a3 = a1p[4];
            #pragma unroll
            for (int nt = 0; nt < 16; nt++) {
                const uint32_t* bp = &sK[(nt * 8 + g) * KSTR + ks * 8 + t];
                mma_tf32(s[nt], a0, a1, a2, a3, bp[0], bp[4]);
            }
        }

        // ---- online softmax ----
        float mx0 = -INFINITY, mx1 = -INFINITY;
        #pragma unroll
        for (int nt = 0; nt < 16; nt++) {
            mx0 = fmaxf(mx0, fmaxf(s[nt][0], s[nt][1]));
            mx1 = fmaxf(mx1, fmaxf(s[nt][2], s[nt][3]));
        }
        mx0 = fmaxf(mx0, __shfl_xor_sync(0xffffffffu, mx0, 1));
        mx0 = fmaxf(mx0, __shfl_xor_sync(0xffffffffu, mx0, 2));
        mx1 = fmaxf(mx1, __shfl_xor_sync(0xffffffffu, mx1, 1));
        mx1 = fmaxf(mx1, __shfl_xor_sync(0xffffffffu, mx1, 2));

        const float mnew0 = fmaxf(m_i[0], mx0);
        const float mnew1 = fmaxf(m_i[1], mx1);
        const float sc0 = __expf(m_i[0] - mnew0);
        const float sc1 = __expf(m_i[1] - mnew1);

        float sum0 = 0.0f, sum1 = 0.0f;
        uint32_t* pr0 = &sP[(wr + g) * PSTR + 2 * t];
        uint32_t* pr1 = pr0 + 8 * PSTR;
        #pragma unroll
        for (int nt = 0; nt < 16; nt++) {
            const float p0 = __expf(s[nt][0] - mnew0);
            const float p1 = __expf(s[nt][1] - mnew0);
            const float p2 = __expf(s[nt][2] - mnew1);
            const float p3 = __expf(s[nt][3] - mnew1);
            sum0 += p0 + p1;
            sum1 += p2 + p3;
            pr0[nt * 8 + 0] = f2tf32(p0);
            pr0[nt * 8 + 1] = f2tf32(p1);
            pr1[nt * 8 + 0] = f2tf32(p2);
            pr1[nt * 8 + 1] = f2tf32(p3);
        }
        sum0 += __shfl_xor_sync(0xffffffffu, sum0, 1);
        sum0 += __shfl_xor_sync(0xffffffffu, sum0, 2);
        sum1 += __shfl_xor_sync(0xffffffffu, sum1, 1);
        sum1 += __shfl_xor_sync(0xffffffffu, sum1, 2);

        l_i[0] = l_i[0] * sc0 + sum0;
        l_i[1] = l_i[1] * sc1 + sum1;
        m_i[0] = mnew0;
        m_i[1] = mnew1;

        #pragma unroll
        for (int nt = 0; nt < 8; nt++) {
            o[nt][0] *= sc0; o[nt][1] *= sc0;
            o[nt][2] *= sc1; o[nt][3] *= sc1;
        }
        __syncwarp();      // sP writes (own rows) visible to own warp

        // ---- O += P * V : warp's 16 rows x 64 cols, K = 128 ----
        #pragma unroll
        for (int ks = 0; ks < 16; ks++) {
            const uint32_t* a0p = &sP[(wr + g) * PSTR + ks * 8 + t];
            const uint32_t* a1p = a0p + 8 * PSTR;
            const uint32_t a0 = a0p[0], a1 = a1p[0], a2 = a0p[4], a3 = a1p[4];
            #pragma unroll
            for (int nt = 0; nt < 8; nt++) {
                const uint32_t* bp = &sV[(ks * 8 + t) * VSTR + nt * 8 + g];
                mma_tf32(o[nt], a0, a1, a2, a3, bp[0], bp[4 * VSTR]);
            }
        }
    }

    // ---- epilogue: O / l -> g_O [b*S+s][h*64+d] ----
    const float inv0 = 1.0f / l_i[0];
    const float inv1 = 1.0f / l_i[1];
    const int b = bh >> 4, h = bh & 15;
    const int row0 = b * S_ + q0 + wr + g;
    const int row1 = row0 + 8;
    #pragma unroll
    for (int nt = 0; nt < 8; nt++) {
        const int n = h * 64 + nt * 8 + 2 * t;
        g_O[(size_t)row0 * 1024 + n]     = o[nt][0] * inv0;
        g_O[(size_t)row0 * 1024 + n + 1] = o[nt][1] * inv0;
        g_O[(size_t)row1 * 1024 + n]     = o[nt][2] * inv1;
        g_O[(size_t)row1 * 1024 + n + 1] = o[nt][3] * inv1;
    }
}

// ---------------------------------------------------------------------------
// kernel_launch
// ---------------------------------------------------------------------------
extern "C" void kernel_launch(void* const* d_in, const int* in_sizes, int n_in,
                              void* d_out, int out_size) {
    const float* X  = (const float*)d_in[0];
    const float* Wq = (const float*)d_in[1];
    const float* bq = (const float*)d_in[2];
    const float* Wk = (const float*)d_in[3];
    const float* bk = (const float*)d_in[4];
    const float* Wv = (const float*)d_in[5];
    const float* bv = (const float*)d_in[6];
    const float* Wo = (const float*)d_in[7];
    const float* bo = (const float*)d_in[8];
    float* out = (float*)d_out;

    cudaFuncSetAttribute(attn_kernel, cudaFuncAttributeMaxDynamicSharedMemorySize,
                         ATTN_SMEM_BYTES);

    qkv_gemm_kernel<<<dim3(8, 64, 3), 256>>>(X, Wq, bq, Wk, bk, Wv, bv);
    attn_kernel<<<dim3(16, 64), 256, ATTN_SMEM_BYTES>>>();
    out_gemm_kernel<<<dim3(8, 64), 256>>>(Wo, bo, out);
}